// round 16
// baseline (speedup 1.0000x reference)
#include <cuda_runtime.h>
#include <cuda_fp16.h>
#include <cstdint>

#define VV 49152
#define NNZ 9
#define GN_N 393216.0f  // V * (C/G)

// ---------------- scratch (device globals; no runtime allocation) ----------------
__device__ __half d_Th[(size_t)8 * VV * 64];   // block1 terms fp16: slot0 = x, 1..7 = t1..t7
__device__ __half d_Uh[(size_t)8 * VV * 128];  // block2 terms fp16: slot0 = normalized h1, 1..7
__device__ __half d_h1[(size_t)VV * 128];      // raw h1pre fp16 (GEMM1 out)
__device__ __half d_res[(size_t)2 * VV * 64];  // residual conv output fp16 [b][v][o]
__device__ float d_stats[8 * 64];              // 8 spread buffers x [GN1 | GN2] (sum,sumsq)x16
__device__ __half d_Bt1h[8 * 128 * 32];        // GEMM1 B^T (W1|Wr) fp16
__device__ __half d_Bt2h[16 * 64 * 32];        // GEMM2 B^T (W2) fp16
__device__ int4 d_colp4[VV * 3];               // padded cols: 12 per row (spmm2)
__device__ float4 d_valp4[VV * 3];             // padded vals: 12 per row (spmm2)
__device__ unsigned int d_bar1;                // grid barrier counter for spmm1 chain
__device__ unsigned int d_bar2;                // grid barrier counter for spmm2 chain

// ---------------- helpers ----------------
__device__ __forceinline__ void mma_f16(float* d, uint32_t a0, uint32_t a1, uint32_t a2,
                                        uint32_t a3, uint32_t b0, uint32_t b1) {
    asm volatile(
        "mma.sync.aligned.m16n8k16.row.col.f32.f16.f16.f32 "
        "{%0,%1,%2,%3}, {%4,%5,%6,%7}, {%8,%9}, {%0,%1,%2,%3};"
        : "+f"(d[0]), "+f"(d[1]), "+f"(d[2]), "+f"(d[3])
        : "r"(a0), "r"(a1), "r"(a2), "r"(a3), "r"(b0), "r"(b1));
}
__device__ __forceinline__ void cpasync16(void* sptr, const void* gptr) {
    uint32_t sa = (uint32_t)__cvta_generic_to_shared(sptr);
    asm volatile("cp.async.cg.shared.global [%0], [%1], 16;" :: "r"(sa), "l"(gptr));
}
#define CP_COMMIT() asm volatile("cp.async.commit_group;" ::: "memory")
#define CP_WAIT(n)  asm volatile("cp.async.wait_group %0;" :: "n"(n) : "memory")

__device__ __forceinline__ void red_stats(float& s, float& s2) {
#pragma unroll
    for (int m = 1; m <= 16; m <<= 1) {
        if (m == 4) continue;
        s += __shfl_xor_sync(0xFFFFFFFFu, s, m);
        s2 += __shfl_xor_sync(0xFFFFFFFFu, s2, m);
    }
}
__device__ __forceinline__ void h8_to_f8(uint4 hv, float* f) {
    float2 q0 = __half22float2(*(__half2*)&hv.x);
    float2 q1 = __half22float2(*(__half2*)&hv.y);
    float2 q2 = __half22float2(*(__half2*)&hv.z);
    float2 q3 = __half22float2(*(__half2*)&hv.w);
    f[0] = q0.x; f[1] = q0.y; f[2] = q1.x; f[3] = q1.y;
    f[4] = q2.x; f[5] = q2.y; f[6] = q3.x; f[7] = q3.y;
}
__device__ __forceinline__ uint4 f8_to_h8(const float* f) {
    uint4 o;
    __half2 h0 = __floats2half2_rn(f[0], f[1]);
    __half2 h1 = __floats2half2_rn(f[2], f[3]);
    __half2 h2 = __floats2half2_rn(f[4], f[5]);
    __half2 h3 = __floats2half2_rn(f[6], f[7]);
    o.x = *(uint32_t*)&h0; o.y = *(uint32_t*)&h1;
    o.z = *(uint32_t*)&h2; o.w = *(uint32_t*)&h3;
    return o;
}
// padded vectorized adjacency (spmm2 form — measured best there)
__device__ __forceinline__ void load_adj(int v, int* c9, float* w9) {
    const int4* cp = d_colp4 + v * 3;
    int4 ca = __ldg(cp), cb = __ldg(cp + 1), cc = __ldg(cp + 2);
    const float4* wp = d_valp4 + v * 3;
    float4 wa = __ldg(wp), wb = __ldg(wp + 1), wc = __ldg(wp + 2);
    c9[0] = ca.x; c9[1] = ca.y; c9[2] = ca.z; c9[3] = ca.w;
    c9[4] = cb.x; c9[5] = cb.y; c9[6] = cb.z; c9[7] = cb.w; c9[8] = cc.x;
    w9[0] = wa.x; w9[1] = wa.y; w9[2] = wa.z; w9[3] = wa.w;
    w9[4] = wb.x; w9[5] = wb.y; w9[6] = wb.z; w9[7] = wb.w; w9[8] = wc.x;
}
// grid-wide barrier: all blocks resident (single wave) — arrive + spin
__device__ __forceinline__ void grid_sync(unsigned int* bar, unsigned int target) {
    __syncthreads();
    __threadfence();
    if (threadIdx.x == 0) {
        atomicAdd(bar, 1u);
        while (*(volatile unsigned int*)bar < target) { __nanosleep(128); }
    }
    __syncthreads();
}

// ---------------- one-time prep ----------------
__global__ void __launch_bounds__(256) k_prep(const float* __restrict__ x,
                                              const float* __restrict__ vals,
                                              const int* __restrict__ cols,
                                              const float* __restrict__ W1,
                                              const float* __restrict__ Wr,
                                              const float* __restrict__ W2) {
    int idx = blockIdx.x * 256 + threadIdx.x;
    if (idx == 0) { d_bar1 = 0u; d_bar2 = 0u; }
    if (idx < 512) { d_stats[idx] = 0.0f; return; }
    idx -= 512;
    if (idx < 32768) {  // Bt1h [kk][o][f]
        int kk = idx >> 12, r = idx & 4095, o = r >> 5, f = r & 31;
        float w = (o < 64) ? W1[kk * 2048 + f * 64 + o] : Wr[kk * 2048 + f * 64 + (o - 64)];
        d_Bt1h[idx] = __float2half(w);
        return;
    }
    idx -= 32768;
    if (idx < 32768) {  // Bt2h [c][o][f]
        int c = idx >> 11, rr = idx & 2047, o = rr >> 5, f = rr & 31;
        int kk = c >> 1, f0 = (c & 1) * 32;
        d_Bt2h[idx] = __float2half(W2[kk * 4096 + (f0 + f) * 64 + o]);
        return;
    }
    idx -= 32768;
    if (idx < VV * 3) {  // cols pad
        int v = idx / 3, j = (idx % 3) * 4;
        int4 o;
        o.x = cols[v * 9 + j];
        o.y = (j + 1 < 9) ? cols[v * 9 + j + 1] : 0;
        o.z = (j + 2 < 9) ? cols[v * 9 + j + 2] : 0;
        o.w = (j + 3 < 9) ? cols[v * 9 + j + 3] : 0;
        d_colp4[idx] = o;
        return;
    }
    idx -= VV * 3;
    if (idx < VV * 3) {  // vals pad
        int v = idx / 3, j = (idx % 3) * 4;
        float4 o;
        o.x = vals[v * 9 + j];
        o.y = (j + 1 < 9) ? vals[v * 9 + j + 1] : 0.f;
        o.z = (j + 2 < 9) ? vals[v * 9 + j + 2] : 0.f;
        o.w = (j + 3 < 9) ? vals[v * 9 + j + 3] : 0.f;
        d_valp4[idx] = o;
        return;
    }
    idx -= VV * 3;
    if (idx < VV * 16) {  // x -> fp16 into d_Th slot0 [v][b*32+f]
        int v = idx >> 4, d = (idx & 15) * 4;
        int b = d >> 5, f = d & 31;
        float4 val = ((const float4*)x)[((size_t)b * VV + v) * 8 + (f >> 2)];
        __half2 h0 = __floats2half2_rn(val.x, val.y);
        __half2 h1 = __floats2half2_rn(val.z, val.w);
        uint2 o;
        o.x = *(uint32_t*)&h0; o.y = *(uint32_t*)&h1;
        *((uint2*)(d_Th) + idx) = o;
    }
}

// ---------------- block1 SPMM chain: all 7 terms, one persistent kernel ----------------
__global__ void __launch_bounds__(256, 7) k_spmm1_chain(const float* __restrict__ vals,
                                                        const int* __restrict__ cols) {
    const int stride = gridDim.x * 256;
#pragma unroll 1
    for (int term = 1; term <= 7; ++term) {
        const uint4* tin = (const uint4*)(d_Th + (size_t)(term - 1) * VV * 64);
        const uint4* tprev = (const uint4*)(d_Th + (size_t)(term >= 2 ? term - 2 : 0) * VV * 64);
        uint4* tout = (uint4*)(d_Th + (size_t)term * VV * 64);
        const bool first = (term == 1);
        for (int tid = blockIdx.x * 256 + threadIdx.x; tid < VV * 8; tid += stride) {
            int v = tid >> 3, d8 = tid & 7;
            float a[8];
#pragma unroll
            for (int i = 0; i < 8; ++i) a[i] = 0.f;
#pragma unroll
            for (int j = 0; j < NNZ; ++j) {
                int c = __ldg(&cols[v * NNZ + j]);
                float w = __ldg(&vals[v * NNZ + j]);
                float t[8];
                h8_to_f8(__ldg(tin + (size_t)c * 8 + d8), t);
#pragma unroll
                for (int i = 0; i < 8; ++i) a[i] += w * t[i];
            }
            if (!first) {
                float p[8];
                h8_to_f8(tprev[tid], p);
#pragma unroll
                for (int i = 0; i < 8; ++i) a[i] = 2.f * a[i] - p[i];
            }
            tout[tid] = f8_to_h8(a);
        }
        if (term < 7) grid_sync(&d_bar1, (unsigned)term * gridDim.x);
    }
}

// ---------------- block2 SPMM chain: all 7 terms, one persistent kernel ----------------
__global__ void __launch_bounds__(256, 5) k_spmm2_chain() {
    const int stride = gridDim.x * 256;
#pragma unroll 1
    for (int term = 1; term <= 7; ++term) {
        const uint4* tin = (const uint4*)(d_Uh + (size_t)(term - 1) * VV * 128);
        const uint4* tprev = (const uint4*)(d_Uh + (size_t)(term >= 2 ? term - 2 : 0) * VV * 128);
        uint4* tout = (uint4*)(d_Uh + (size_t)term * VV * 128);
        const bool first = (term == 1);
        for (int tid = blockIdx.x * 256 + threadIdx.x; tid < VV * 16; tid += stride) {
            int v = tid >> 4, d8 = tid & 15;
            int c9[9]; float w9[9];
            load_adj(v, c9, w9);
            float a[8];
#pragma unroll
            for (int i = 0; i < 8; ++i) a[i] = 0.f;
#pragma unroll
            for (int j = 0; j < NNZ; ++j) {
                float t[8];
                h8_to_f8(__ldg(tin + (size_t)c9[j] * 16 + d8), t);
#pragma unroll
                for (int i = 0; i < 8; ++i) a[i] += w9[j] * t[i];
            }
            if (!first) {
                float p[8];
                h8_to_f8(tprev[tid], p);
#pragma unroll
                for (int i = 0; i < 8; ++i) a[i] = 2.f * a[i] - p[i];
            }
            tout[tid] = f8_to_h8(a);
        }
        if (term < 7) grid_sync(&d_bar2, (unsigned)term * gridDim.x);
    }
}

// ---------------- GEMM 1: [98304 x 256] @ [256 x 128] (W1|Wr), fp16 mma, 3-stage ---------
__global__ void __launch_bounds__(256) k_gemm1_mma(const float* __restrict__ x,
                                                   const float* __restrict__ b1,
                                                   const float* __restrict__ br) {
    extern __shared__ __align__(16) char smem[];
    __half (*As)[128][40] = (__half(*)[128][40])smem;              // 3 x 10240 B
    __half (*Bs)[128][40] = (__half(*)[128][40])(smem + 30720);    // 3 x 10240 B
    int v0 = blockIdx.x * 64;
    int tid = threadIdx.x;
    int warp = tid >> 5, lane = tid & 31;
    int g = lane >> 2, t = lane & 3;
    int wm = warp >> 1, wn = warp & 1;
    int m_w = wm * 32, n_w = wn * 64;

    float acc[2][8][4];
#pragma unroll
    for (int mi = 0; mi < 2; ++mi)
#pragma unroll
        for (int ni = 0; ni < 8; ++ni)
#pragma unroll
            for (int q = 0; q < 4; ++q) acc[mi][ni][q] = 0.f;

    auto stageB = [&](int c, int buf) {
        const __half* bsrc = d_Bt1h + c * 4096;
#pragma unroll
        for (int tl = 0; tl < 2; ++tl) {
            int q = tid + tl * 256;
            int o = q >> 2, p = q & 3;
            cpasync16(&Bs[buf][o][p * 8], bsrc + o * 32 + p * 8);
        }
    };
    auto stageA = [&](int c, int buf) {  // c >= 1
        const __half* asrc = d_Th + (size_t)c * VV * 64 + (size_t)v0 * 64;
#pragma unroll
        for (int tl = 0; tl < 2; ++tl) {
            int q = tid + tl * 256;
            int r = q >> 2, p = q & 3;
            cpasync16(&As[buf][r][p * 8], asrc + (r >> 1) * 64 + (r & 1) * 32 + p * 8);
        }
    };

    {
        const float4* xs = (const float4*)x;
#pragma unroll
        for (int tl = 0; tl < 4; ++tl) {
            int lt4 = tid + tl * 256;
            int voff = lt4 >> 4, bb = (lt4 >> 3) & 1, f4 = lt4 & 7;
            float4 val = xs[((size_t)bb * VV + v0 + voff) * 8 + f4];
            __half2 h0 = __floats2half2_rn(val.x, val.y);
            __half2 h1 = __floats2half2_rn(val.z, val.w);
            uint2 o;
            o.x = *(uint32_t*)&h0; o.y = *(uint32_t*)&h1;
            *(uint2*)&As[0][voff * 2 + bb][f4 * 4] = o;
        }
        stageB(0, 0);
        CP_COMMIT();
        stageA(1, 1); stageB(1, 1);
        CP_COMMIT();
    }
#pragma unroll 1
    for (int c = 0; c < 8; ++c) {
        int cb = c - (c / 3) * 3;
        if (c < 6) {
            int nb = (c + 2) - ((c + 2) / 3) * 3;
            stageA(c + 2, nb); stageB(c + 2, nb);
            CP_COMMIT();
            CP_WAIT(2);
        } else if (c == 6) {
            CP_WAIT(1);
        } else {
            CP_WAIT(0);
        }
        __syncthreads();
#pragma unroll
        for (int ks = 0; ks < 2; ++ks) {
            int k0 = ks * 16;
            uint32_t a[2][4];
#pragma unroll
            for (int mi = 0; mi < 2; ++mi) {
                int m = m_w + mi * 16;
                a[mi][0] = *(uint32_t*)&As[cb][m + g][k0 + 2 * t];
                a[mi][1] = *(uint32_t*)&As[cb][m + g + 8][k0 + 2 * t];
                a[mi][2] = *(uint32_t*)&As[cb][m + g][k0 + 2 * t + 8];
                a[mi][3] = *(uint32_t*)&As[cb][m + g + 8][k0 + 2 * t + 8];
            }
#pragma unroll
            for (int ni = 0; ni < 8; ++ni) {
                int n = n_w + ni * 8;
                uint32_t b0 = *(uint32_t*)&Bs[cb][n + g][k0 + 2 * t];
                uint32_t b1v = *(uint32_t*)&Bs[cb][n + g][k0 + 2 * t + 8];
#pragma unroll
                for (int mi = 0; mi < 2; ++mi)
                    mma_f16(acc[mi][ni], a[mi][0], a[mi][1], a[mi][2], a[mi][3], b0, b1v);
            }
        }
        __syncthreads();
    }
    // epilogue + fused GN1 stats (fp32 accs); h1pre -> d_h1 fp16, res -> d_res fp16
    float sni[8], s2ni[8];
#pragma unroll
    for (int ni = 0; ni < 8; ++ni) { sni[ni] = 0.f; s2ni[ni] = 0.f; }
#pragma unroll
    for (int mi = 0; mi < 2; ++mi) {
        int r1 = m_w + mi * 16 + g;
        int v1 = v0 + (r1 >> 1), bb1 = r1 & 1;
        int r2 = r1 + 8;
        int v2 = v0 + (r2 >> 1), bb2 = r2 & 1;
#pragma unroll
        for (int ni = 0; ni < 8; ++ni) {
            int n = n_w + ni * 8 + t * 2;
            float2 p1 = make_float2(acc[mi][ni][0], acc[mi][ni][1]);
            float2 p2 = make_float2(acc[mi][ni][2], acc[mi][ni][3]);
            if (n < 64) {
                float bx = __ldg(&b1[n]), by = __ldg(&b1[n + 1]);
                p1.x += bx; p1.y += by; p2.x += bx; p2.y += by;
                *(__half2*)(d_h1 + (size_t)v1 * 128 + bb1 * 64 + n) = __floats2half2_rn(p1.x, p1.y);
                *(__half2*)(d_h1 + (size_t)v2 * 128 + bb2 * 64 + n) = __floats2half2_rn(p2.x, p2.y);
                sni[ni] += p1.x + p1.y + p2.x + p2.y;
                s2ni[ni] += p1.x * p1.x + p1.y * p1.y + p2.x * p2.x + p2.y * p2.y;
            } else {
                int o = n - 64;
                float bx = __ldg(&br[o]), by = __ldg(&br[o + 1]);
                p1.x += bx; p1.y += by; p2.x += bx; p2.y += by;
                *(__half2*)(d_res + (size_t)bb1 * VV * 64 + (size_t)v1 * 64 + o) = __floats2half2_rn(p1.x, p1.y);
                *(__half2*)(d_res + (size_t)bb2 * VV * 64 + (size_t)v2 * 64 + o) = __floats2half2_rn(p2.x, p2.y);
            }
        }
    }
    if (wn == 0) {
        float* sb = d_stats + (blockIdx.x & 7) * 64;
#pragma unroll
        for (int ni = 0; ni < 8; ++ni) {
            float s = sni[ni], s2 = s2ni[ni];
            red_stats(s, s2);
            if ((lane & 0x1B) == 0) {
                int bb = (lane >> 2) & 1;
                atomicAdd(&sb[(bb * 8 + ni) * 2], s);
                atomicAdd(&sb[(bb * 8 + ni) * 2 + 1], s2);
            }
        }
    }
}

// ---------------- GEMM 2: [98304 x 512] @ [512 x 64] (W2), fp16 mma, 3-stage -------------
__global__ void __launch_bounds__(256) k_gemm2_mma(const float* __restrict__ b2,
                                                   float* __restrict__ out) {
    extern __shared__ __align__(16) char smem[];
    __half (*As)[128][40] = (__half(*)[128][40])smem;              // 3 x 10240 B
    __half (*Bs)[64][40] = (__half(*)[64][40])(smem + 30720);      // 3 x 5120 B
    int v0 = blockIdx.x * 64;
    int tid = threadIdx.x;
    int warp = tid >> 5, lane = tid & 31;
    int g = lane >> 2, t = lane & 3;
    int m_w = warp * 16;

    float acc[8][4];
#pragma unroll
    for (int ni = 0; ni < 8; ++ni)
#pragma unroll
        for (int q = 0; q < 4; ++q) acc[ni][q] = 0.f;

    auto stage = [&](int c, int buf) {
        int kk = c >> 1, f0 = (c & 1) * 32;
        const __half* asrc = d_Uh + (size_t)kk * VV * 128 + (size_t)v0 * 128 + f0;
#pragma unroll
        for (int tl = 0; tl < 2; ++tl) {
            int q = tid + tl * 256;
            int r = q >> 2, p = q & 3;
            cpasync16(&As[buf][r][p * 8], asrc + (r >> 1) * 128 + (r & 1) * 64 + p * 8);
        }
        const __half* bsrc = d_Bt2h + c * 2048;
        {
            int q = tid;
            int o = q >> 2, p = q & 3;
            cpasync16(&Bs[buf][o][p * 8], bsrc + o * 32 + p * 8);
        }
    };

    stage(0, 0); CP_COMMIT();
    stage(1, 1); CP_COMMIT();
#pragma unroll 1
    for (int c = 0; c < 16; ++c) {
        int cb = c - (c / 3) * 3;
        if (c < 14) {
            int nb = (c + 2) - ((c + 2) / 3) * 3;
            stage(c + 2, nb);
            CP_COMMIT();
            CP_WAIT(2);
        } else if (c == 14) {
            CP_WAIT(1);
        } else {
            CP_WAIT(0);
        }
        __syncthreads();
#pragma unroll
        for (int ks = 0; ks < 2; ++ks) {
            int k0 = ks * 16;
            uint32_t a0 = *(uint32_t*)&As[cb][m_w + g][k0 + 2 * t];
            uint32_t a1 = *(uint32_t*)&As[cb][m_w + g + 8][k0 + 2 * t];
            uint32_t a2 = *(uint32_t*)&As[cb][m_w + g][k0 + 2 * t + 8];
            uint32_t a3 = *(uint32_t*)&As[cb][m_w + g + 8][k0 + 2 * t + 8];
#pragma unroll
            for (int ni = 0; ni < 8; ++ni) {
                int n = ni * 8;
                uint32_t b0 = *(uint32_t*)&Bs[cb][n + g][k0 + 2 * t];
                uint32_t b1v = *(uint32_t*)&Bs[cb][n + g][k0 + 2 * t + 8];
                mma_f16(acc[ni], a0, a1, a2, a3, b0, b1v);
            }
        }
        __syncthreads();
    }
    int r1 = m_w + g;
    int v1 = v0 + (r1 >> 1), bb1 = r1 & 1;
    int r2 = r1 + 8;
    int v2 = v0 + (r2 >> 1), bb2 = r2 & 1;
    float* o1 = out + (size_t)bb1 * VV * 64 + (size_t)v1 * 64;
    float* o2 = out + (size_t)bb2 * VV * 64 + (size_t)v2 * 64;
    float* sb = d_stats + (blockIdx.x & 7) * 64;
#pragma unroll
    for (int ni = 0; ni < 8; ++ni) {
        int n = ni * 8 + t * 2;
        float bx = __ldg(&b2[n]), by = __ldg(&b2[n + 1]);
        float e0 = acc[ni][0] + bx, e1 = acc[ni][1] + by;
        float e2 = acc[ni][2] + bx, e3 = acc[ni][3] + by;
        *(float2*)(o1 + n) = make_float2(e0, e1);
        *(float2*)(o2 + n) = make_float2(e2, e3);
        float s = e0 + e1 + e2 + e3;
        float s2 = e0 * e0 + e1 * e1 + e2 * e2 + e3 * e3;
        red_stats(s, s2);
        if ((lane & 0x1B) == 0) {
            int bb = (lane >> 2) & 1;
            atomicAdd(&sb[32 + (bb * 8 + ni) * 2], s);
            atomicAdd(&sb[32 + (bb * 8 + ni) * 2 + 1], s2);
        }
    }
}

// ---------------- GN1 apply + LeakyReLU: d_h1 (fp16) -> d_Uh slot0 (fp16) ----------------
__global__ void __launch_bounds__(256) k_gnapply1(const float* __restrict__ gamma,
                                                  const float* __restrict__ beta) {
    int tid = blockIdx.x * 256 + threadIdx.x;  // over VV*128/4
    int idx = tid * 4;
    int rem = idx & 127, b = rem >> 6, c0 = rem & 63, g = c0 >> 3;
    int bin = (b * 8 + g) * 2;
    float s = 0.f, s2 = 0.f;
#pragma unroll
    for (int p = 0; p < 8; ++p) { s += d_stats[p * 64 + bin]; s2 += d_stats[p * 64 + bin + 1]; }
    float mu = s / GN_N;
    float var = s2 / GN_N - mu * mu;
    float rstd = rsqrtf(var + 1e-5f);
    uint2 hv = ((const uint2*)d_h1)[tid];
    float2 va = __half22float2(*(__half2*)&hv.x);
    float2 vb = __half22float2(*(__half2*)&hv.y);
    float y0 = (va.x - mu) * rstd * __ldg(&gamma[c0 + 0]) + __ldg(&beta[c0 + 0]);
    float y1 = (va.y - mu) * rstd * __ldg(&gamma[c0 + 1]) + __ldg(&beta[c0 + 1]);
    float y2 = (vb.x - mu) * rstd * __ldg(&gamma[c0 + 2]) + __ldg(&beta[c0 + 2]);
    float y3 = (vb.y - mu) * rstd * __ldg(&gamma[c0 + 3]) + __ldg(&beta[c0 + 3]);
    y0 = fmaxf(y0, 0.1f * y0); y1 = fmaxf(y1, 0.1f * y1);
    y2 = fmaxf(y2, 0.1f * y2); y3 = fmaxf(y3, 0.1f * y3);
    __half2 h0 = __floats2half2_rn(y0, y1);
    __half2 h1 = __floats2half2_rn(y2, y3);
    uint2 o;
    o.x = *(uint32_t*)&h0; o.y = *(uint32_t*)&h1;
    *((uint2*)d_Uh + tid) = o;
}

// ---------------- final: out = leaky(GN2(h2pre)) + res (float4 / fp16 res) ----------------
__global__ void __launch_bounds__(256) k_final(float* __restrict__ out,
                                               const float* __restrict__ gamma,
                                               const float* __restrict__ beta) {
    int tid = blockIdx.x * 256 + threadIdx.x;  // over 2*VV*16
    int idx = tid * 4;
    int b = (idx >= VV * 64) ? 1 : 0;
    int c0 = idx & 63, g = c0 >> 3;
    int bin = 32 + (b * 8 + g) * 2;
    float s = 0.f, s2 = 0.f;
#pragma unroll
    for (int p = 0; p < 8; ++p) { s += d_stats[p * 64 + bin]; s2 += d_stats[p * 64 + bin + 1]; }
    float mu = s / GN_N;
    float var = s2 / GN_N - mu * mu;
    float rstd = rsqrtf(var + 1e-5f);
    float4 v = *(const float4*)(out + idx);
    uint2 rh = ((const uint2*)d_res)[tid];
    float2 ra = __half22float2(*(__half2*)&rh.x);
    float2 rb = __half22float2(*(__half2*)&rh.y);
    float y0 = (v.x - mu) * rstd * __ldg(&gamma[c0 + 0]) + __ldg(&beta[c0 + 0]);
    float y1 = (v.y - mu) * rstd * __ldg(&gamma[c0 + 1]) + __ldg(&beta[c0 + 1]);
    float y2 = (v.z - mu) * rstd * __ldg(&gamma[c0 + 2]) + __ldg(&beta[c0 + 2]);
    float y3 = (v.w - mu) * rstd * __ldg(&gamma[c0 + 3]) + __ldg(&beta[c0 + 3]);
    float4 o;
    o.x = fmaxf(y0, 0.1f * y0) + ra.x;
    o.y = fmaxf(y1, 0.1f * y1) + ra.y;
    o.z = fmaxf(y2, 0.1f * y2) + rb.x;
    o.w = fmaxf(y3, 0.1f * y3) + rb.y;
    *(float4*)(out + idx) = o;
}

// ---------------- launch ----------------
extern "C" void kernel_launch(void* const* d_in, const int* in_sizes, int n_in,
                              void* d_out, int out_size) {
    const float* x    = (const float*)d_in[0];
    const float* vals = (const float*)d_in[1];
    const int*   cols = (const int*)d_in[3];
    const float* W1 = (const float*)d_in[4];
    const float* b1 = (const float*)d_in[5];
    const float* g1 = (const float*)d_in[6];
    const float* be1 = (const float*)d_in[7];
    const float* W2 = (const float*)d_in[8];
    const float* b2 = (const float*)d_in[9];
    const float* g2 = (const float*)d_in[10];
    const float* be2 = (const float*)d_in[11];
    const float* Wr = (const float*)d_in[12];
    const float* br = (const float*)d_in[13];
    float* out = (float*)d_out;

    const int SMEM1 = 3 * 128 * 40 * 2 * 2;               // 61440 B
    const int SMEM2 = 3 * 128 * 40 * 2 + 3 * 64 * 40 * 2; // 46080 B
    cudaFuncSetAttribute(k_gemm1_mma, cudaFuncAttributeMaxDynamicSharedMemorySize, SMEM1);
    cudaFuncSetAttribute(k_gemm2_mma, cudaFuncAttributeMaxDynamicSharedMemorySize, SMEM2);

    const int prep_total = 512 + 32768 + 32768 + VV * 3 + VV * 3 + VV * 16;
    k_prep<<<(prep_total + 255) / 256, 256>>>(x, vals, cols, W1, Wr, W2);

    // block1 Chebyshev chain t1..t7 — ONE persistent kernel, grid barrier between terms.
    // __launch_bounds__(256, 7) guarantees >= 7 blocks/SM residency => 1036 all resident.
    const int G1 = 148 * 7;
    k_spmm1_chain<<<G1, 256>>>(vals, cols);

    // h1pre (fp16 -> d_h1) + residual (fp16) + fused GN1 stats
    k_gemm1_mma<<<VV / 64, 256, SMEM1>>>(x, b1, br);

    // GN1 apply: d_h1 -> d_Uh slot0 (fp16)
    k_gnapply1<<<(VV * 128 / 4) / 256, 256>>>(g1, be1);

    // block2 Chebyshev chain u1..u7 — ONE persistent kernel.
    // __launch_bounds__(256, 5) guarantees >= 5 blocks/SM residency => 740 all resident.
    const int G2 = 148 * 5;
    k_spmm2_chain<<<G2, 256>>>();

    // h2pre -> out + fused GN2 stats
    k_gemm2_mma<<<VV / 64, 256, SMEM2>>>(b2, out);

    // GN2 + LeakyReLU + residual add
    k_final<<<(2 * VV * 16) / 256, 256>>>(out, g2, be2);
}

// round 17
// speedup vs baseline: 1.1479x; 1.1479x over previous
#include <cuda_runtime.h>
#include <cuda_fp16.h>
#include <cstdint>

#define VV 49152
#define NNZ 9
#define GN_N 393216.0f  // V * (C/G)

// ---------------- scratch (device globals; no runtime allocation) ----------------
__device__ __half d_Th[(size_t)8 * VV * 64];   // block1 terms fp16: slot0 = x, 1..7 = t1..t7
__device__ __half d_Uh[(size_t)8 * VV * 128];  // block2 terms fp16: slot0 = normalized h1, 1..7
__device__ __half d_h1[(size_t)VV * 128];      // raw h1pre fp16 (GEMM1 out)
__device__ __half d_res[(size_t)2 * VV * 64];  // residual conv output fp16 [b][v][o]
__device__ float d_stats[8 * 64];              // 8 spread buffers x [GN1 | GN2] (sum,sumsq)x16
__device__ __half d_Bt1h[8 * 128 * 32];        // GEMM1 B^T (W1|Wr) fp16
__device__ __half d_Bt2h[16 * 64 * 32];        // GEMM2 B^T (W2) fp16
__device__ int4 d_colp4[VV * 3];               // padded cols: 12 per row (spmm2)
__device__ float4 d_valp4[VV * 3];             // padded vals: 12 per row (spmm2)

// ---------------- helpers ----------------
__device__ __forceinline__ void mma_f16(float* d, uint32_t a0, uint32_t a1, uint32_t a2,
                                        uint32_t a3, uint32_t b0, uint32_t b1) {
    asm volatile(
        "mma.sync.aligned.m16n8k16.row.col.f32.f16.f16.f32 "
        "{%0,%1,%2,%3}, {%4,%5,%6,%7}, {%8,%9}, {%0,%1,%2,%3};"
        : "+f"(d[0]), "+f"(d[1]), "+f"(d[2]), "+f"(d[3])
        : "r"(a0), "r"(a1), "r"(a2), "r"(a3), "r"(b0), "r"(b1));
}
__device__ __forceinline__ void cpasync16(void* sptr, const void* gptr) {
    uint32_t sa = (uint32_t)__cvta_generic_to_shared(sptr);
    asm volatile("cp.async.cg.shared.global [%0], [%1], 16;" :: "r"(sa), "l"(gptr));
}
#define CP_COMMIT() asm volatile("cp.async.commit_group;" ::: "memory")
#define CP_WAIT(n)  asm volatile("cp.async.wait_group %0;" :: "n"(n) : "memory")

__device__ __forceinline__ void red_stats(float& s, float& s2) {
#pragma unroll
    for (int m = 1; m <= 16; m <<= 1) {
        if (m == 4) continue;
        s += __shfl_xor_sync(0xFFFFFFFFu, s, m);
        s2 += __shfl_xor_sync(0xFFFFFFFFu, s2, m);
    }
}
__device__ __forceinline__ void h8_to_f8(uint4 hv, float* f) {
    float2 q0 = __half22float2(*(__half2*)&hv.x);
    float2 q1 = __half22float2(*(__half2*)&hv.y);
    float2 q2 = __half22float2(*(__half2*)&hv.z);
    float2 q3 = __half22float2(*(__half2*)&hv.w);
    f[0] = q0.x; f[1] = q0.y; f[2] = q1.x; f[3] = q1.y;
    f[4] = q2.x; f[5] = q2.y; f[6] = q3.x; f[7] = q3.y;
}
__device__ __forceinline__ uint4 f8_to_h8(const float* f) {
    uint4 o;
    __half2 h0 = __floats2half2_rn(f[0], f[1]);
    __half2 h1 = __floats2half2_rn(f[2], f[3]);
    __half2 h2 = __floats2half2_rn(f[4], f[5]);
    __half2 h3 = __floats2half2_rn(f[6], f[7]);
    o.x = *(uint32_t*)&h0; o.y = *(uint32_t*)&h1;
    o.z = *(uint32_t*)&h2; o.w = *(uint32_t*)&h3;
    return o;
}
// padded vectorized adjacency (spmm2 form — measured best there)
__device__ __forceinline__ void load_adj(int v, int* c9, float* w9) {
    const int4* cp = d_colp4 + v * 3;
    int4 ca = __ldg(cp), cb = __ldg(cp + 1), cc = __ldg(cp + 2);
    const float4* wp = d_valp4 + v * 3;
    float4 wa = __ldg(wp), wb = __ldg(wp + 1), wc = __ldg(wp + 2);
    c9[0] = ca.x; c9[1] = ca.y; c9[2] = ca.z; c9[3] = ca.w;
    c9[4] = cb.x; c9[5] = cb.y; c9[6] = cb.z; c9[7] = cb.w; c9[8] = cc.x;
    w9[0] = wa.x; w9[1] = wa.y; w9[2] = wa.z; w9[3] = wa.w;
    w9[4] = wb.x; w9[5] = wb.y; w9[6] = wb.z; w9[7] = wb.w; w9[8] = wc.x;
}
// build per-block GN scale/shift table (128 entries: b*64 + c)
__device__ __forceinline__ void gn_table(int stats_off, const float* __restrict__ gamma,
                                         const float* __restrict__ beta,
                                         float* scl, float* sft) {
    int tid = threadIdx.x;
    if (tid < 128) {
        int b = tid >> 6, c = tid & 63, g = c >> 3;
        int bin = stats_off + (b * 8 + g) * 2;
        float s = 0.f, s2 = 0.f;
#pragma unroll
        for (int p = 0; p < 8; ++p) { s += d_stats[p * 64 + bin]; s2 += d_stats[p * 64 + bin + 1]; }
        float mu = s / GN_N;
        float var = s2 / GN_N - mu * mu;
        float rstd = rsqrtf(var + 1e-5f);
        float sc = rstd * __ldg(&gamma[c]);
        scl[tid] = sc;
        sft[tid] = __ldg(&beta[c]) - mu * sc;
    }
    __syncthreads();
}

// ---------------- one-time prep ----------------
__global__ void __launch_bounds__(256) k_prep(const float* __restrict__ x,
                                              const float* __restrict__ vals,
                                              const int* __restrict__ cols,
                                              const float* __restrict__ W1,
                                              const float* __restrict__ Wr,
                                              const float* __restrict__ W2) {
    int idx = blockIdx.x * 256 + threadIdx.x;
    if (idx < 512) { d_stats[idx] = 0.0f; return; }
    idx -= 512;
    if (idx < 32768) {  // Bt1h [kk][o][f]
        int kk = idx >> 12, r = idx & 4095, o = r >> 5, f = r & 31;
        float w = (o < 64) ? W1[kk * 2048 + f * 64 + o] : Wr[kk * 2048 + f * 64 + (o - 64)];
        d_Bt1h[idx] = __float2half(w);
        return;
    }
    idx -= 32768;
    if (idx < 32768) {  // Bt2h [c][o][f]
        int c = idx >> 11, rr = idx & 2047, o = rr >> 5, f = rr & 31;
        int kk = c >> 1, f0 = (c & 1) * 32;
        d_Bt2h[idx] = __float2half(W2[kk * 4096 + (f0 + f) * 64 + o]);
        return;
    }
    idx -= 32768;
    if (idx < VV * 3) {  // cols pad
        int v = idx / 3, j = (idx % 3) * 4;
        int4 o;
        o.x = cols[v * 9 + j];
        o.y = (j + 1 < 9) ? cols[v * 9 + j + 1] : 0;
        o.z = (j + 2 < 9) ? cols[v * 9 + j + 2] : 0;
        o.w = (j + 3 < 9) ? cols[v * 9 + j + 3] : 0;
        d_colp4[idx] = o;
        return;
    }
    idx -= VV * 3;
    if (idx < VV * 3) {  // vals pad
        int v = idx / 3, j = (idx % 3) * 4;
        float4 o;
        o.x = vals[v * 9 + j];
        o.y = (j + 1 < 9) ? vals[v * 9 + j + 1] : 0.f;
        o.z = (j + 2 < 9) ? vals[v * 9 + j + 2] : 0.f;
        o.w = (j + 3 < 9) ? vals[v * 9 + j + 3] : 0.f;
        d_valp4[idx] = o;
        return;
    }
    idx -= VV * 3;
    if (idx < VV * 16) {  // x -> fp16 into d_Th slot0 [v][b*32+f]
        int v = idx >> 4, d = (idx & 15) * 4;
        int b = d >> 5, f = d & 31;
        float4 val = ((const float4*)x)[((size_t)b * VV + v) * 8 + (f >> 2)];
        __half2 h0 = __floats2half2_rn(val.x, val.y);
        __half2 h1 = __floats2half2_rn(val.z, val.w);
        uint2 o;
        o.x = *(uint32_t*)&h0; o.y = *(uint32_t*)&h1;
        *((uint2*)(d_Th) + idx) = o;
    }
}

// ---------------- block1 SPMM (fp16, 8 halves/thread, scalar adjacency) ----------------
template <bool FIRST>
__global__ void __launch_bounds__(256) k_spmm1(int kin, int kp2, int kout,
                                               const float* __restrict__ vals,
                                               const int* __restrict__ cols) {
    int tid = blockIdx.x * 256 + threadIdx.x;  // over VV*8
    int v = tid >> 3, d8 = tid & 7;
    const uint4* tin = (const uint4*)(d_Th + (size_t)kin * VV * 64);
    float a[8];
#pragma unroll
    for (int i = 0; i < 8; ++i) a[i] = 0.f;
#pragma unroll
    for (int j = 0; j < NNZ; ++j) {
        int c = __ldg(&cols[v * NNZ + j]);
        float w = __ldg(&vals[v * NNZ + j]);
        float t[8];
        h8_to_f8(__ldg(tin + (size_t)c * 8 + d8), t);
#pragma unroll
        for (int i = 0; i < 8; ++i) a[i] += w * t[i];
    }
    if (!FIRST) {
        float p[8];
        h8_to_f8(((const uint4*)(d_Th + (size_t)kp2 * VV * 64))[tid], p);
#pragma unroll
        for (int i = 0; i < 8; ++i) a[i] = 2.f * a[i] - p[i];
    }
    ((uint4*)(d_Th + (size_t)kout * VV * 64))[tid] = f8_to_h8(a);
}

// ---------------- block2 SPMM (fp16, 8 halves/thread, padded adjacency) ----------------
template <bool FIRST>
__global__ void __launch_bounds__(256) k_spmm2(int kin, int kp2, int kout) {
    int tid = blockIdx.x * 256 + threadIdx.x;  // over VV*16
    int v = tid >> 4, d8 = tid & 15;
    int c9[9]; float w9[9];
    load_adj(v, c9, w9);
    const uint4* tin = (const uint4*)(d_Uh + (size_t)kin * VV * 128);
    float a[8];
#pragma unroll
    for (int i = 0; i < 8; ++i) a[i] = 0.f;
#pragma unroll
    for (int j = 0; j < NNZ; ++j) {
        float t[8];
        h8_to_f8(__ldg(tin + (size_t)c9[j] * 16 + d8), t);
#pragma unroll
        for (int i = 0; i < 8; ++i) a[i] += w9[j] * t[i];
    }
    if (!FIRST) {
        float p[8];
        h8_to_f8(((const uint4*)(d_Uh + (size_t)kp2 * VV * 128))[tid], p);
#pragma unroll
        for (int i = 0; i < 8; ++i) a[i] = 2.f * a[i] - p[i];
    }
    ((uint4*)(d_Uh + (size_t)kout * VV * 128))[tid] = f8_to_h8(a);
}

// ---------------- GEMM 1: [98304 x 256] @ [256 x 128] (W1|Wr), fp16 mma, 3-stage ---------
__global__ void __launch_bounds__(256) k_gemm1_mma(const float* __restrict__ x,
                                                   const float* __restrict__ b1,
                                                   const float* __restrict__ br) {
    extern __shared__ __align__(16) char smem[];
    __half (*As)[128][40] = (__half(*)[128][40])smem;              // 3 x 10240 B
    __half (*Bs)[128][40] = (__half(*)[128][40])(smem + 30720);    // 3 x 10240 B
    int v0 = blockIdx.x * 64;
    int tid = threadIdx.x;
    int warp = tid >> 5, lane = tid & 31;
    int g = lane >> 2, t = lane & 3;
    int wm = warp >> 1, wn = warp & 1;
    int m_w = wm * 32, n_w = wn * 64;

    float acc[2][8][4];
#pragma unroll
    for (int mi = 0; mi < 2; ++mi)
#pragma unroll
        for (int ni = 0; ni < 8; ++ni)
#pragma unroll
            for (int q = 0; q < 4; ++q) acc[mi][ni][q] = 0.f;

    auto stageB = [&](int c, int buf) {
        const __half* bsrc = d_Bt1h + c * 4096;
#pragma unroll
        for (int tl = 0; tl < 2; ++tl) {
            int q = tid + tl * 256;
            int o = q >> 2, p = q & 3;
            cpasync16(&Bs[buf][o][p * 8], bsrc + o * 32 + p * 8);
        }
    };
    auto stageA = [&](int c, int buf) {  // c >= 1
        const __half* asrc = d_Th + (size_t)c * VV * 64 + (size_t)v0 * 64;
#pragma unroll
        for (int tl = 0; tl < 2; ++tl) {
            int q = tid + tl * 256;
            int r = q >> 2, p = q & 3;
            cpasync16(&As[buf][r][p * 8], asrc + (r >> 1) * 64 + (r & 1) * 32 + p * 8);
        }
    };

    {
        const float4* xs = (const float4*)x;
#pragma unroll
        for (int tl = 0; tl < 4; ++tl) {
            int lt4 = tid + tl * 256;
            int voff = lt4 >> 4, bb = (lt4 >> 3) & 1, f4 = lt4 & 7;
            float4 val = xs[((size_t)bb * VV + v0 + voff) * 8 + f4];
            __half2 h0 = __floats2half2_rn(val.x, val.y);
            __half2 h1 = __floats2half2_rn(val.z, val.w);
            uint2 o;
            o.x = *(uint32_t*)&h0; o.y = *(uint32_t*)&h1;
            *(uint2*)&As[0][voff * 2 + bb][f4 * 4] = o;
        }
        stageB(0, 0);
        CP_COMMIT();
        stageA(1, 1); stageB(1, 1);
        CP_COMMIT();
    }
#pragma unroll 1
    for (int c = 0; c < 8; ++c) {
        int cb = c - (c / 3) * 3;
        if (c < 6) {
            int nb = (c + 2) - ((c + 2) / 3) * 3;
            stageA(c + 2, nb); stageB(c + 2, nb);
            CP_COMMIT();
            CP_WAIT(2);
        } else if (c == 6) {
            CP_WAIT(1);
        } else {
            CP_WAIT(0);
        }
        __syncthreads();
#pragma unroll
        for (int ks = 0; ks < 2; ++ks) {
            int k0 = ks * 16;
            uint32_t a[2][4];
#pragma unroll
            for (int mi = 0; mi < 2; ++mi) {
                int m = m_w + mi * 16;
                a[mi][0] = *(uint32_t*)&As[cb][m + g][k0 + 2 * t];
                a[mi][1] = *(uint32_t*)&As[cb][m + g + 8][k0 + 2 * t];
                a[mi][2] = *(uint32_t*)&As[cb][m + g][k0 + 2 * t + 8];
                a[mi][3] = *(uint32_t*)&As[cb][m + g + 8][k0 + 2 * t + 8];
            }
#pragma unroll
            for (int ni = 0; ni < 8; ++ni) {
                int n = n_w + ni * 8;
                uint32_t b0 = *(uint32_t*)&Bs[cb][n + g][k0 + 2 * t];
                uint32_t b1v = *(uint32_t*)&Bs[cb][n + g][k0 + 2 * t + 8];
#pragma unroll
                for (int mi = 0; mi < 2; ++mi)
                    mma_f16(acc[mi][ni], a[mi][0], a[mi][1], a[mi][2], a[mi][3], b0, b1v);
            }
        }
        __syncthreads();
    }
    // epilogue + fused GN1 stats (fp32 accs); h1pre -> d_h1 fp16, res -> d_res fp16
    float sni[8], s2ni[8];
#pragma unroll
    for (int ni = 0; ni < 8; ++ni) { sni[ni] = 0.f; s2ni[ni] = 0.f; }
#pragma unroll
    for (int mi = 0; mi < 2; ++mi) {
        int r1 = m_w + mi * 16 + g;
        int v1 = v0 + (r1 >> 1), bb1 = r1 & 1;
        int r2 = r1 + 8;
        int v2 = v0 + (r2 >> 1), bb2 = r2 & 1;
#pragma unroll
        for (int ni = 0; ni < 8; ++ni) {
            int n = n_w + ni * 8 + t * 2;
            float2 p1 = make_float2(acc[mi][ni][0], acc[mi][ni][1]);
            float2 p2 = make_float2(acc[mi][ni][2], acc[mi][ni][3]);
            if (n < 64) {
                float bx = __ldg(&b1[n]), by = __ldg(&b1[n + 1]);
                p1.x += bx; p1.y += by; p2.x += bx; p2.y += by;
                *(__half2*)(d_h1 + (size_t)v1 * 128 + bb1 * 64 + n) = __floats2half2_rn(p1.x, p1.y);
                *(__half2*)(d_h1 + (size_t)v2 * 128 + bb2 * 64 + n) = __floats2half2_rn(p2.x, p2.y);
                sni[ni] += p1.x + p1.y + p2.x + p2.y;
                s2ni[ni] += p1.x * p1.x + p1.y * p1.y + p2.x * p2.x + p2.y * p2.y;
            } else {
                int o = n - 64;
                float bx = __ldg(&br[o]), by = __ldg(&br[o + 1]);
                p1.x += bx; p1.y += by; p2.x += bx; p2.y += by;
                *(__half2*)(d_res + (size_t)bb1 * VV * 64 + (size_t)v1 * 64 + o) = __floats2half2_rn(p1.x, p1.y);
                *(__half2*)(d_res + (size_t)bb2 * VV * 64 + (size_t)v2 * 64 + o) = __floats2half2_rn(p2.x, p2.y);
            }
        }
    }
    if (wn == 0) {
        float* sb = d_stats + (blockIdx.x & 7) * 64;
#pragma unroll
        for (int ni = 0; ni < 8; ++ni) {
            float s = sni[ni], s2 = s2ni[ni];
            red_stats(s, s2);
            if ((lane & 0x1B) == 0) {
                int bb = (lane >> 2) & 1;
                atomicAdd(&sb[(bb * 8 + ni) * 2], s);
                atomicAdd(&sb[(bb * 8 + ni) * 2 + 1], s2);
            }
        }
    }
}

// ---------------- GEMM 2: [98304 x 512] @ [512 x 64] (W2), fp16 mma, 3-stage -------------
__global__ void __launch_bounds__(256) k_gemm2_mma(const float* __restrict__ b2,
                                                   float* __restrict__ out) {
    extern __shared__ __align__(16) char smem[];
    __half (*As)[128][40] = (__half(*)[128][40])smem;              // 3 x 10240 B
    __half (*Bs)[64][40] = (__half(*)[64][40])(smem + 30720);      // 3 x 5120 B
    int v0 = blockIdx.x * 64;
    int tid = threadIdx.x;
    int warp = tid >> 5, lane = tid & 31;
    int g = lane >> 2, t = lane & 3;
    int m_w = warp * 16;

    float acc[8][4];
#pragma unroll
    for (int ni = 0; ni < 8; ++ni)
#pragma unroll
        for (int q = 0; q < 4; ++q) acc[ni][q] = 0.f;

    auto stage = [&](int c, int buf) {
        int kk = c >> 1, f0 = (c & 1) * 32;
        const __half* asrc = d_Uh + (size_t)kk * VV * 128 + (size_t)v0 * 128 + f0;
#pragma unroll
        for (int tl = 0; tl < 2; ++tl) {
            int q = tid + tl * 256;
            int r = q >> 2, p = q & 3;
            cpasync16(&As[buf][r][p * 8], asrc + (r >> 1) * 128 + (r & 1) * 64 + p * 8);
        }
        const __half* bsrc = d_Bt2h + c * 2048;
        {
            int q = tid;
            int o = q >> 2, p = q & 3;
            cpasync16(&Bs[buf][o][p * 8], bsrc + o * 32 + p * 8);
        }
    };

    stage(0, 0); CP_COMMIT();
    stage(1, 1); CP_COMMIT();
#pragma unroll 1
    for (int c = 0; c < 16; ++c) {
        int cb = c - (c / 3) * 3;
        if (c < 14) {
            int nb = (c + 2) - ((c + 2) / 3) * 3;
            stage(c + 2, nb);
            CP_COMMIT();
            CP_WAIT(2);
        } else if (c == 14) {
            CP_WAIT(1);
        } else {
            CP_WAIT(0);
        }
        __syncthreads();
#pragma unroll
        for (int ks = 0; ks < 2; ++ks) {
            int k0 = ks * 16;
            uint32_t a0 = *(uint32_t*)&As[cb][m_w + g][k0 + 2 * t];
            uint32_t a1 = *(uint32_t*)&As[cb][m_w + g + 8][k0 + 2 * t];
            uint32_t a2 = *(uint32_t*)&As[cb][m_w + g][k0 + 2 * t + 8];
            uint32_t a3 = *(uint32_t*)&As[cb][m_w + g + 8][k0 + 2 * t + 8];
#pragma unroll
            for (int ni = 0; ni < 8; ++ni) {
                int n = ni * 8;
                uint32_t b0 = *(uint32_t*)&Bs[cb][n + g][k0 + 2 * t];
                uint32_t b1v = *(uint32_t*)&Bs[cb][n + g][k0 + 2 * t + 8];
                mma_f16(acc[ni], a0, a1, a2, a3, b0, b1v);
            }
        }
        __syncthreads();
    }
    int r1 = m_w + g;
    int v1 = v0 + (r1 >> 1), bb1 = r1 & 1;
    int r2 = r1 + 8;
    int v2 = v0 + (r2 >> 1), bb2 = r2 & 1;
    float* o1 = out + (size_t)bb1 * VV * 64 + (size_t)v1 * 64;
    float* o2 = out + (size_t)bb2 * VV * 64 + (size_t)v2 * 64;
    float* sb = d_stats + (blockIdx.x & 7) * 64;
#pragma unroll
    for (int ni = 0; ni < 8; ++ni) {
        int n = ni * 8 + t * 2;
        float bx = __ldg(&b2[n]), by = __ldg(&b2[n + 1]);
        float e0 = acc[ni][0] + bx, e1 = acc[ni][1] + by;
        float e2 = acc[ni][2] + bx, e3 = acc[ni][3] + by;
        *(float2*)(o1 + n) = make_float2(e0, e1);
        *(float2*)(o2 + n) = make_float2(e2, e3);
        float s = e0 + e1 + e2 + e3;
        float s2 = e0 * e0 + e1 * e1 + e2 * e2 + e3 * e3;
        red_stats(s, s2);
        if ((lane & 0x1B) == 0) {
            int bb = (lane >> 2) & 1;
            atomicAdd(&sb[32 + (bb * 8 + ni) * 2], s);
            atomicAdd(&sb[32 + (bb * 8 + ni) * 2 + 1], s2);
        }
    }
}

// ---------------- GN1 apply + LeakyReLU: d_h1 (fp16) -> d_Uh slot0 (fp16) ----------------
// smem scale/shift table computed once per block; grid-stride bulk loop.
__global__ void __launch_bounds__(256) k_gnapply1(const float* __restrict__ gamma,
                                                  const float* __restrict__ beta) {
    __shared__ float scl[128], sft[128];
    gn_table(0, gamma, beta, scl, sft);
    const int total = VV * 32;  // uint2 elements
    const int stride = gridDim.x * 256;
    for (int tid = blockIdx.x * 256 + threadIdx.x; tid < total; tid += stride) {
        int rem = (tid * 4) & 127;  // b*64 + c0
        uint2 hv = ((const uint2*)d_h1)[tid];
        float2 va = __half22float2(*(__half2*)&hv.x);
        float2 vb = __half22float2(*(__half2*)&hv.y);
        float y0 = fmaf(va.x, scl[rem + 0], sft[rem + 0]);
        float y1 = fmaf(va.y, scl[rem + 1], sft[rem + 1]);
        float y2 = fmaf(vb.x, scl[rem + 2], sft[rem + 2]);
        float y3 = fmaf(vb.y, scl[rem + 3], sft[rem + 3]);
        y0 = fmaxf(y0, 0.1f * y0); y1 = fmaxf(y1, 0.1f * y1);
        y2 = fmaxf(y2, 0.1f * y2); y3 = fmaxf(y3, 0.1f * y3);
        __half2 h0 = __floats2half2_rn(y0, y1);
        __half2 h1 = __floats2half2_rn(y2, y3);
        uint2 o;
        o.x = *(uint32_t*)&h0; o.y = *(uint32_t*)&h1;
        ((uint2*)d_Uh)[tid] = o;
    }
}

// ---------------- final: out = leaky(GN2(h2pre)) + res ----------------
__global__ void __launch_bounds__(256) k_final(float* __restrict__ out,
                                               const float* __restrict__ gamma,
                                               const float* __restrict__ beta) {
    __shared__ float scl[128], sft[128];
    gn_table(32, gamma, beta, scl, sft);
    const int total = 2 * VV * 16;  // float4 elements
    const int stride = gridDim.x * 256;
    for (int tid = blockIdx.x * 256 + threadIdx.x; tid < total; tid += stride) {
        int idx = tid * 4;
        int boff = (idx >= VV * 64) ? 64 : 0;
        int e = boff + (idx & 63);
        float4 v = *(const float4*)(out + idx);
        uint2 rh = ((const uint2*)d_res)[tid];
        float2 ra = __half22float2(*(__half2*)&rh.x);
        float2 rb = __half22float2(*(__half2*)&rh.y);
        float y0 = fmaf(v.x, scl[e + 0], sft[e + 0]);
        float y1 = fmaf(v.y, scl[e + 1], sft[e + 1]);
        float y2 = fmaf(v.z, scl[e + 2], sft[e + 2]);
        float y3 = fmaf(v.w, scl[e + 3], sft[e + 3]);
        float4 o;
        o.x = fmaxf(y0, 0.1f * y0) + ra.x;
        o.y = fmaxf(y1, 0.1f * y1) + ra.y;
        o.z = fmaxf(y2, 0.1f * y2) + rb.x;
        o.w = fmaxf(y3, 0.1f * y3) + rb.y;
        *(float4*)(out + idx) = o;
    }
}

// ---------------- launch ----------------
extern "C" void kernel_launch(void* const* d_in, const int* in_sizes, int n_in,
                              void* d_out, int out_size) {
    const float* x    = (const float*)d_in[0];
    const float* vals = (const float*)d_in[1];
    const int*   cols = (const int*)d_in[3];
    const float* W1 = (const float*)d_in[4];
    const float* b1 = (const float*)d_in[5];
    const float* g1 = (const float*)d_in[6];
    const float* be1 = (const float*)d_in[7];
    const float* W2 = (const float*)d_in[8];
    const float* b2 = (const float*)d_in[9];
    const float* g2 = (const float*)d_in[10];
    const float* be2 = (const float*)d_in[11];
    const float* Wr = (const float*)d_in[12];
    const float* br = (const float*)d_in[13];
    float* out = (float*)d_out;

    const int SMEM1 = 3 * 128 * 40 * 2 * 2;               // 61440 B
    const int SMEM2 = 3 * 128 * 40 * 2 + 3 * 64 * 40 * 2; // 46080 B
    cudaFuncSetAttribute(k_gemm1_mma, cudaFuncAttributeMaxDynamicSharedMemorySize, SMEM1);
    cudaFuncSetAttribute(k_gemm2_mma, cudaFuncAttributeMaxDynamicSharedMemorySize, SMEM2);

    const int prep_total = 512 + 32768 + 32768 + VV * 3 + VV * 3 + VV * 16;
    k_prep<<<(prep_total + 255) / 256, 256>>>(x, vals, cols, W1, Wr, W2);

    // block1 Chebyshev terms t1..t7 (fp16)
    const int g1d = (VV * 8) / 256;
    k_spmm1<true><<<g1d, 256>>>(0, 0, 1, vals, cols);
    k_spmm1<false><<<g1d, 256>>>(1, 0, 2, vals, cols);
    k_spmm1<false><<<g1d, 256>>>(2, 1, 3, vals, cols);
    k_spmm1<false><<<g1d, 256>>>(3, 2, 4, vals, cols);
    k_spmm1<false><<<g1d, 256>>>(4, 3, 5, vals, cols);
    k_spmm1<false><<<g1d, 256>>>(5, 4, 6, vals, cols);
    k_spmm1<false><<<g1d, 256>>>(6, 5, 7, vals, cols);

    // h1pre (fp16 -> d_h1) + residual (fp16) + fused GN1 stats
    k_gemm1_mma<<<VV / 64, 256, SMEM1>>>(x, b1, br);

    // GN1 apply: d_h1 -> d_Uh slot0 (fp16); smem table + grid-stride
    k_gnapply1<<<148 * 8, 256>>>(g1, be1);

    // block2 Chebyshev terms u1..u7 (fp16)
    const int g2d = (VV * 16) / 256;
    k_spmm2<true><<<g2d, 256>>>(0, 0, 1);
    k_spmm2<false><<<g2d, 256>>>(1, 0, 2);
    k_spmm2<false><<<g2d, 256>>>(2, 1, 3);
    k_spmm2<false><<<g2d, 256>>>(3, 2, 4);
    k_spmm2<false><<<g2d, 256>>>(4, 3, 5);
    k_spmm2<false><<<g2d, 256>>>(5, 4, 6);
    k_spmm2<false><<<g2d, 256>>>(6, 5, 7);

    // h2pre -> out + fused GN2 stats
    k_gemm2_mma<<<VV / 64, 256, SMEM2>>>(b2, out);

    // GN2 + LeakyReLU + residual add; smem table + grid-stride
    k_final<<<148 * 8, 256>>>(out, g2, be2);
}